// round 1
// baseline (speedup 1.0000x reference)
#include <cuda_runtime.h>

#define NODES_MAX 50000
#define F 128

// Scratch (no runtime allocation allowed)
__device__ float g_P[NODES_MAX * F];       // h @ W1h^T + b1
__device__ float g_sums[NODES_MAX * F];    // segment sums of leaky(per-edge act)
__device__ float g_counts[NODES_MAX];      // in-degree (float)
__device__ float g_W1T[F * F];             // [k][c] = W1[c*131 + k]   (k < 128 part)
__device__ float g_W2T[256 * F];           // [k][c] = W2[c*256 + k]

// ---------------------------------------------------------------------------
// Prep: transpose weight matrices for coalesced GEMM B-loads; zero accumulators
// ---------------------------------------------------------------------------
__global__ void prep_kernel(const float* __restrict__ W1,
                            const float* __restrict__ W2,
                            int n_nodes)
{
    int idx = blockIdx.x * blockDim.x + threadIdx.x;
    int stride = gridDim.x * blockDim.x;

    for (int i = idx; i < F * F; i += stride) {
        int c = i / F, k = i % F;
        g_W1T[k * F + c] = W1[c * 131 + k];
    }
    for (int i = idx; i < 256 * F; i += stride) {
        int c = i / 256, k = i % 256;
        g_W2T[k * F + c] = W2[c * 256 + k];
    }
    int nsum4 = (n_nodes * F) / 4;
    float4* s4 = reinterpret_cast<float4*>(g_sums);
    float4 z = make_float4(0.f, 0.f, 0.f, 0.f);
    for (int i = idx; i < nsum4; i += stride) s4[i] = z;
    for (int i = idx; i < n_nodes; i += stride) g_counts[i] = 0.f;
}

// ---------------------------------------------------------------------------
// GEMM1: P[n][c] = sum_k h[n][k] * W1[c][k] + b1[c]     (M x 128, K = 128)
// Block: 64 rows x 128 cols, 256 threads, 8x4 micro-tile, BK = 16
// ---------------------------------------------------------------------------
__global__ __launch_bounds__(256) void gemm1_kernel(
    const float* __restrict__ h, const float* __restrict__ b1, int M)
{
    __shared__ float As[16][68];   // [k][m], padded to dodge STS conflicts
    __shared__ float Bs[16][128];  // [k][c]

    const int tid  = threadIdx.x;
    const int row0 = blockIdx.x * 64;
    const int tx   = tid & 31;   // col group (x4)
    const int ty   = tid >> 5;   // row group (x8)

    float acc[8][4] = {};

    for (int k0 = 0; k0 < 128; k0 += 16) {
        // Load A tile: one float4 per thread
        {
            int m  = tid >> 2;
            int kq = tid & 3;
            int gr = row0 + m;
            float4 v = make_float4(0.f, 0.f, 0.f, 0.f);
            if (gr < M) v = *(const float4*)(h + gr * 128 + k0 + kq * 4);
            As[kq * 4 + 0][m] = v.x;
            As[kq * 4 + 1][m] = v.y;
            As[kq * 4 + 2][m] = v.z;
            As[kq * 4 + 3][m] = v.w;
        }
        // Load B tile from transposed weights: coalesced float4
        #pragma unroll
        for (int i = tid; i < 512; i += 256) {
            int k = i >> 5, cq = i & 31;
            *(float4*)&Bs[k][cq * 4] =
                *(const float4*)(g_W1T + (k0 + k) * 128 + cq * 4);
        }
        __syncthreads();

        #pragma unroll
        for (int k = 0; k < 16; k++) {
            float a[8], b[4];
            *(float4*)&a[0] = *(const float4*)&As[k][ty * 8];
            *(float4*)&a[4] = *(const float4*)&As[k][ty * 8 + 4];
            *(float4*)&b[0] = *(const float4*)&Bs[k][tx * 4];
            #pragma unroll
            for (int i2 = 0; i2 < 8; i2++)
                #pragma unroll
                for (int j = 0; j < 4; j++)
                    acc[i2][j] = fmaf(a[i2], b[j], acc[i2][j]);
        }
        __syncthreads();
    }

    int c = tx * 4;
    float4 bias = *(const float4*)(b1 + c);
    #pragma unroll
    for (int i = 0; i < 8; i++) {
        int gr = row0 + ty * 8 + i;
        if (gr < M) {
            float4 o = make_float4(acc[i][0] + bias.x, acc[i][1] + bias.y,
                                   acc[i][2] + bias.z, acc[i][3] + bias.w);
            *(float4*)(g_P + gr * 128 + c) = o;
        }
    }
}

// ---------------------------------------------------------------------------
// Edge kernel: one warp per edge (grid-stride).
// t = leaky( P[src] + w0*W1[:,128] + w1*W1[:,129] + w2*W1[:,130] )
// red.global.add.v4.f32 into g_sums[dst]; count bump by lane 0.
// ---------------------------------------------------------------------------
__global__ __launch_bounds__(256) void edge_kernel(
    const int* __restrict__ src, const int* __restrict__ dst,
    const float* __restrict__ ew, const float* __restrict__ W1, int E)
{
    __shared__ float cw[3][128];
    for (int i = threadIdx.x; i < 384; i += 256) {
        int t = i >> 7, j = i & 127;
        cw[t][j] = W1[j * 131 + 128 + t];
    }
    __syncthreads();

    const int lane = threadIdx.x & 31;
    const int col  = lane * 4;
    const float c00 = cw[0][col], c01 = cw[0][col + 1], c02 = cw[0][col + 2], c03 = cw[0][col + 3];
    const float c10 = cw[1][col], c11 = cw[1][col + 1], c12 = cw[1][col + 2], c13 = cw[1][col + 3];
    const float c20 = cw[2][col], c21 = cw[2][col + 1], c22 = cw[2][col + 2], c23 = cw[2][col + 3];

    int gwarp  = (blockIdx.x * 256 + threadIdx.x) >> 5;
    int nwarps = (gridDim.x * 256) >> 5;

    for (int e = gwarp; e < E; e += nwarps) {
        int s = src[e];
        int d = dst[e];
        float w0 = ew[e * 3 + 0];
        float w1 = ew[e * 3 + 1];
        float w2 = ew[e * 3 + 2];

        float4 p = *(const float4*)(g_P + s * 128 + col);
        float t0 = p.x + w0 * c00 + w1 * c10 + w2 * c20;
        float t1 = p.y + w0 * c01 + w1 * c11 + w2 * c21;
        float t2 = p.z + w0 * c02 + w1 * c12 + w2 * c22;
        float t3 = p.w + w0 * c03 + w1 * c13 + w2 * c23;
        t0 = (t0 < 0.f) ? 0.01f * t0 : t0;
        t1 = (t1 < 0.f) ? 0.01f * t1 : t1;
        t2 = (t2 < 0.f) ? 0.01f * t2 : t2;
        t3 = (t3 < 0.f) ? 0.01f * t3 : t3;

        float* addr = g_sums + d * 128 + col;
        asm volatile("red.global.add.v4.f32 [%0], {%1, %2, %3, %4};"
                     :: "l"(addr), "f"(t0), "f"(t1), "f"(t2), "f"(t3)
                     : "memory");
        if (lane == 0) atomicAdd(&g_counts[d], 1.0f);
    }
}

// ---------------------------------------------------------------------------
// GEMM2: out[n][c] = relu( sum_{k<128} h[n][k]*W2[c][k]
//                        + sum_{k<128} (sums[n][k]/max(cnt,1))*W2[c][128+k] + b2[c] )
// Same tiling as gemm1 but K = 256; second half of K reads sums * inv(count).
// ---------------------------------------------------------------------------
__global__ __launch_bounds__(256) void gemm2_kernel(
    const float* __restrict__ h, const float* __restrict__ b2,
    float* __restrict__ out, int M)
{
    __shared__ float As[16][68];
    __shared__ float Bs[16][128];
    __shared__ float inv[64];

    const int tid  = threadIdx.x;
    const int row0 = blockIdx.x * 64;
    const int tx   = tid & 31;
    const int ty   = tid >> 5;

    if (tid < 64) {
        int gr = row0 + tid;
        inv[tid] = (gr < M) ? (1.0f / fmaxf(g_counts[gr], 1.0f)) : 0.f;
    }
    __syncthreads();

    float acc[8][4] = {};

    for (int k0 = 0; k0 < 256; k0 += 16) {
        {
            int m  = tid >> 2;
            int kq = tid & 3;
            int gr = row0 + m;
            float4 v = make_float4(0.f, 0.f, 0.f, 0.f);
            if (gr < M) {
                if (k0 < 128) {
                    v = *(const float4*)(h + gr * 128 + k0 + kq * 4);
                } else {
                    v = *(const float4*)(g_sums + gr * 128 + (k0 - 128) + kq * 4);
                    float sc = inv[m];
                    v.x *= sc; v.y *= sc; v.z *= sc; v.w *= sc;
                }
            }
            As[kq * 4 + 0][m] = v.x;
            As[kq * 4 + 1][m] = v.y;
            As[kq * 4 + 2][m] = v.z;
            As[kq * 4 + 3][m] = v.w;
        }
        #pragma unroll
        for (int i = tid; i < 512; i += 256) {
            int k = i >> 5, cq = i & 31;
            *(float4*)&Bs[k][cq * 4] =
                *(const float4*)(g_W2T + (k0 + k) * 128 + cq * 4);
        }
        __syncthreads();

        #pragma unroll
        for (int k = 0; k < 16; k++) {
            float a[8], b[4];
            *(float4*)&a[0] = *(const float4*)&As[k][ty * 8];
            *(float4*)&a[4] = *(const float4*)&As[k][ty * 8 + 4];
            *(float4*)&b[0] = *(const float4*)&Bs[k][tx * 4];
            #pragma unroll
            for (int i2 = 0; i2 < 8; i2++)
                #pragma unroll
                for (int j = 0; j < 4; j++)
                    acc[i2][j] = fmaf(a[i2], b[j], acc[i2][j]);
        }
        __syncthreads();
    }

    int c = tx * 4;
    float4 bias = *(const float4*)(b2 + c);
    #pragma unroll
    for (int i = 0; i < 8; i++) {
        int gr = row0 + ty * 8 + i;
        if (gr < M) {
            float4 o;
            o.x = fmaxf(acc[i][0] + bias.x, 0.f);
            o.y = fmaxf(acc[i][1] + bias.y, 0.f);
            o.z = fmaxf(acc[i][2] + bias.z, 0.f);
            o.w = fmaxf(acc[i][3] + bias.w, 0.f);
            *(float4*)(out + gr * 128 + c) = o;
        }
    }
}

// ---------------------------------------------------------------------------
extern "C" void kernel_launch(void* const* d_in, const int* in_sizes, int n_in,
                              void* d_out, int out_size)
{
    const float* h    = (const float*)d_in[0];
    const int*   esrc = (const int*)  d_in[1];
    const int*   edst = (const int*)  d_in[2];
    const float* ew   = (const float*)d_in[3];
    const float* W1   = (const float*)d_in[4];
    const float* b1   = (const float*)d_in[5];
    const float* W2   = (const float*)d_in[6];
    const float* b2   = (const float*)d_in[7];
    float* out = (float*)d_out;

    int M = in_sizes[0] / 128;   // 50000 nodes
    int E = in_sizes[1];         // 800000 edges

    prep_kernel<<<512, 256>>>(W1, W2, M);
    gemm1_kernel<<<(M + 63) / 64, 256>>>(h, b1, M);
    edge_kernel<<<2368, 256>>>(esrc, edst, ew, W1, E);
    gemm2_kernel<<<(M + 63) / 64, 256>>>(h, b2, out, M);
}